// round 2
// baseline (speedup 1.0000x reference)
#include <cuda_runtime.h>
#include <math.h>

#define MAXN 100000
#define MAXE 1600000

// ---------------- scratch (static device arrays; no allocation) ----------------
__device__ float g_dinv[MAXN];            // deg accum, then rsqrt(deg)
__device__ int   g_cnt[MAXN];
__device__ int   g_cur[MAXN];
__device__ int   g_offs[MAXN + 1];
__device__ int2  g_edge[MAXE];            // {src, bitcast(norm)} CSR payload
__device__ float g_A2[(size_t)MAXN * 192];// [XA(128) | h(64)] per node
__device__ float g_P[(size_t)MAXN * 192]; // [Zpre' | Rpre' | Ht_partial]
__device__ float g_W2[192 * 192];
__device__ float g_c[192];

// ---------------- f32x2 packed-FMA helpers (sm_103a FFMA2) ----------------
__device__ __forceinline__ unsigned long long pack2(float v) {
    unsigned long long r;
    asm("mov.b64 %0, {%1, %1};" : "=l"(r) : "f"(v));
    return r;
}
__device__ __forceinline__ unsigned long long fma2(unsigned long long a,
                                                   unsigned long long b,
                                                   unsigned long long c) {
    unsigned long long d;
    asm("fma.rn.f32x2 %0, %1, %2, %3;" : "=l"(d) : "l"(a), "l"(b), "l"(c));
    return d;
}

// ---------------- setup: init + W2 fold + bias fold (one launch) ----------------
__global__ void k_setup(const float* __restrict__ Wz, const float* __restrict__ Wr,
                        const float* __restrict__ Wh, const float* __restrict__ Lz,
                        const float* __restrict__ Lr, const float* __restrict__ Lh,
                        const float* __restrict__ bz, const float* __restrict__ br,
                        const float* __restrict__ bh, const float* __restrict__ bLz,
                        const float* __restrict__ bLr, const float* __restrict__ bLh,
                        int n) {
    int i = blockIdx.x * blockDim.x + threadIdx.x;
    if (i < n) { g_dinv[i] = 1.0f; g_cnt[i] = 0; g_cur[i] = 0; }
    if (i < 192 * 192) {
        int k = i / 192, j = i % 192;
        float val;
        if (k < 128) {
            int g = j >> 6, jj = j & 63;
            const float* W = (g == 0) ? Wz : ((g == 1) ? Wr : Wh);
            const float* L = (g == 0) ? Lz : ((g == 1) ? Lr : Lh);
            float s = 0.f;
            #pragma unroll 8
            for (int m = 0; m < 64; m++) s = fmaf(W[k * 64 + m], L[m * 64 + jj], s);
            val = s;
        } else {
            int kk = k - 128;
            if (j < 64)       val = Lz[(64 + kk) * 64 + j];
            else if (j < 128) val = Lr[(64 + kk) * 64 + (j - 64)];
            else              val = 0.f;       // (h*R) @ Lh_bot handled in finalize
        }
        g_W2[i] = val;
    }
    if (i < 192) {
        int g = i >> 6, jj = i & 63;
        const float* b  = (g == 0) ? bz  : ((g == 1) ? br  : bh);
        const float* L  = (g == 0) ? Lz  : ((g == 1) ? Lr  : Lh);
        const float* bL = (g == 0) ? bLz : ((g == 1) ? bLr : bLh);
        float s = bL[jj];
        #pragma unroll 8
        for (int m = 0; m < 64; m++) s = fmaf(b[m], L[m * 64 + jj], s);
        g_c[i] = s;
    }
}

// ---------------- degree histogram ----------------
__global__ void k_hist(const int* __restrict__ ei, const float* __restrict__ ew, int E) {
    int e = blockIdx.x * blockDim.x + threadIdx.x;
    if (e < E) {
        int c = ei[E + e];
        atomicAdd(&g_dinv[c], ew[e]);
        atomicAdd(&g_cnt[c], 1);
    }
}

// ---------------- dinv + exclusive scan, single block ----------------
__global__ void k_scan1(int n, int E) {
    int tid = threadIdx.x;
    for (int i = tid; i < n; i += 1024) g_dinv[i] = rsqrtf(g_dinv[i]);  // deg>=1 (self-loop)

    __shared__ int s[1024];
    int per = (n + 1023) >> 10;
    int start = tid * per;
    int end = start + per; if (end > n) end = n; if (start > n) start = n;
    int sum = 0;
    for (int i = start; i < end; i++) sum += g_cnt[i];
    s[tid] = sum; __syncthreads();
    int v = sum;
    for (int d = 1; d < 1024; d <<= 1) {
        int t = (tid >= d) ? s[tid - d] : 0;
        __syncthreads();
        s[tid] += t;
        __syncthreads();
    }
    int pre = s[tid] - v;
    for (int i = start; i < end; i++) { g_offs[i] = pre; pre += g_cnt[i]; }
    if (tid == 0) g_offs[n] = E;
}

// ---------------- CSR fill ----------------
__global__ void k_fill(const int* __restrict__ ei, const float* __restrict__ ew, int E) {
    int e = blockIdx.x * blockDim.x + threadIdx.x;
    if (e < E) {
        int r = ei[e];
        int c = ei[E + e];
        float nrm = g_dinv[r] * ew[e] * g_dinv[c];
        int pos = g_offs[c] + atomicAdd(&g_cur[c], 1);
        g_edge[pos] = make_int2(r, __float_as_int(nrm));
    }
}

// ---------------- aggregation + h copy: A2 = [XA | h] ----------------
__global__ __launch_bounds__(256) void k_agg(const float* __restrict__ x,
                                             const float* __restrict__ h, int n) {
    int warp = threadIdx.x >> 5, lane = threadIdx.x & 31;
    int node = blockIdx.x * 8 + warp;
    if (node >= n) return;
    const float4* xv = (const float4*)x;
    float di = g_dinv[node];
    float s = di * di;
    float4 a = xv[(size_t)node * 32 + lane];
    float4 acc = make_float4(s * a.x, s * a.y, s * a.z, s * a.w);
    int j = g_offs[node], j1 = g_offs[node + 1];
    for (; j + 1 < j1; j += 2) {
        int2 e0 = g_edge[j], e1 = g_edge[j + 1];
        float4 v0 = xv[(size_t)e0.x * 32 + lane];
        float4 v1 = xv[(size_t)e1.x * 32 + lane];
        float w0 = __int_as_float(e0.y), w1 = __int_as_float(e1.y);
        acc.x = fmaf(w0, v0.x, acc.x); acc.y = fmaf(w0, v0.y, acc.y);
        acc.z = fmaf(w0, v0.z, acc.z); acc.w = fmaf(w0, v0.w, acc.w);
        acc.x = fmaf(w1, v1.x, acc.x); acc.y = fmaf(w1, v1.y, acc.y);
        acc.z = fmaf(w1, v1.z, acc.z); acc.w = fmaf(w1, v1.w, acc.w);
    }
    if (j < j1) {
        int2 e0 = g_edge[j];
        float4 v0 = xv[(size_t)e0.x * 32 + lane];
        float w0 = __int_as_float(e0.y);
        acc.x = fmaf(w0, v0.x, acc.x); acc.y = fmaf(w0, v0.y, acc.y);
        acc.z = fmaf(w0, v0.z, acc.z); acc.w = fmaf(w0, v0.w, acc.w);
    }
    ((float4*)g_A2)[(size_t)node * 48 + lane] = acc;
    if (lane < 16)
        ((float4*)g_A2)[(size_t)node * 48 + 32 + lane] =
            ((const float4*)h)[(size_t)node * 16 + lane];
}

// ---------------- GEMM: P[N,192] = A2[N,192] @ W2[192,192], FFMA2 inner loop ----------------
__global__ __launch_bounds__(256) void k_gemm(int n) {
    __shared__ float As[32][132];     // transposed A tile, padded
    __shared__ float Bs[32 * 192];
    const float* A = g_A2;
    const float* B = g_W2;
    float* C = g_P;
    int tid = threadIdx.x;
    int rowBase = blockIdx.x * 128;
    int ty = tid >> 4, tx = tid & 15;

    unsigned long long acc[8][6];     // 8 rows x 12 cols as 6 f32x2 pairs
    #pragma unroll
    for (int i = 0; i < 8; i++)
        #pragma unroll
        for (int jx = 0; jx < 6; jx++) acc[i][jx] = 0ull;

    for (int k0 = 0; k0 < 192; k0 += 32) {
        // stage B slice (32 x 192)
        const float4* Bg = (const float4*)(B + k0 * 192);
        float4* Bsv = (float4*)Bs;
        #pragma unroll
        for (int q = 0; q < 6; q++) Bsv[tid + q * 256] = Bg[tid + q * 256];
        // stage A slice transposed
        int m = tid >> 1, kh = (tid & 1) * 16;
        int r = rowBase + m;
        const float* Ar = A + (size_t)r * 192 + k0 + kh;
        #pragma unroll
        for (int q = 0; q < 4; q++) {
            float4 v = (r < n) ? *(const float4*)(Ar + 4 * q) : make_float4(0.f, 0.f, 0.f, 0.f);
            As[kh + 4 * q + 0][m] = v.x;
            As[kh + 4 * q + 1][m] = v.y;
            As[kh + 4 * q + 2][m] = v.z;
            As[kh + 4 * q + 3][m] = v.w;
        }
        __syncthreads();
        #pragma unroll
        for (int k = 0; k < 32; k++) {
            unsigned long long b[6];
            const float2* bp = (const float2*)(Bs + k * 192 + tx * 12);
            #pragma unroll
            for (int jx = 0; jx < 6; jx++) {
                float2 t = bp[jx];
                b[jx] = *reinterpret_cast<unsigned long long*>(&t);
            }
            float a[8];
            #pragma unroll
            for (int i = 0; i < 8; i++) a[i] = As[k][ty * 8 + i];
            #pragma unroll
            for (int i = 0; i < 8; i++) {
                unsigned long long pa = pack2(a[i]);
                #pragma unroll
                for (int jx = 0; jx < 6; jx++)
                    acc[i][jx] = fma2(pa, b[jx], acc[i][jx]);
            }
        }
        __syncthreads();
    }
    #pragma unroll
    for (int i = 0; i < 8; i++) {
        int row = rowBase + ty * 8 + i;
        if (row < n) {
            float2* Crow = (float2*)(C + (size_t)row * 192 + tx * 12);
            #pragma unroll
            for (int jx = 0; jx < 6; jx++)
                Crow[jx] = *reinterpret_cast<float2*>(&acc[i][jx]);
        }
    }
}

// ---------------- finalize: gates, (h*R)@Lh_bot, GRU blend, head ----------------
__device__ __forceinline__ float sigf(float v) { return 1.f / (1.f + __expf(-v)); }

__global__ __launch_bounds__(256) void k_final(const float* __restrict__ h,
                                               const float* __restrict__ Lh,
                                               const float* __restrict__ Wo,
                                               const float* __restrict__ bo,
                                               float* __restrict__ out, int n) {
    __shared__ float Lhb[64][65];
    __shared__ float sWo[64];
    __shared__ float sc[192];
    int tid = threadIdx.x;
    for (int i = tid; i < 4096; i += 256) {
        int k = i >> 6, j = i & 63;
        Lhb[k][j] = Lh[(64 + k) * 64 + j];
    }
    if (tid < 64) sWo[tid] = Wo[tid];
    if (tid < 192) sc[tid] = g_c[tid];
    __syncthreads();

    int warp = tid >> 5, lane = tid & 31;
    int node = blockIdx.x * 8 + warp;
    if (node >= n) return;

    const float* p = g_P + (size_t)node * 192;
    float z0 = sigf(p[lane]       + sc[lane]);
    float z1 = sigf(p[lane + 32]  + sc[lane + 32]);
    float r0 = sigf(p[lane + 64]  + sc[lane + 64]);
    float r1 = sigf(p[lane + 96]  + sc[lane + 96]);
    float q0 =      p[lane + 128] + sc[lane + 128];
    float q1 =      p[lane + 160] + sc[lane + 160];

    float h0 = h[(size_t)node * 64 + lane];
    float h1 = h[(size_t)node * 64 + lane + 32];
    float v0 = h0 * r0, v1 = h1 * r1;

    float acc0 = q0, acc1 = q1;
    #pragma unroll
    for (int k = 0; k < 32; k++) {
        float vk = __shfl_sync(0xffffffffu, v0, k);
        acc0 = fmaf(vk, Lhb[k][lane], acc0);
        acc1 = fmaf(vk, Lhb[k][lane + 32], acc1);
    }
    #pragma unroll
    for (int k = 0; k < 32; k++) {
        float vk = __shfl_sync(0xffffffffu, v1, k);
        acc0 = fmaf(vk, Lhb[k + 32][lane], acc0);
        acc1 = fmaf(vk, Lhb[k + 32][lane + 32], acc1);
    }
    float t0 = tanhf(acc0), t1 = tanhf(acc1);
    float hn0 = z0 * h0 + (1.f - z0) * t0;
    float hn1 = z1 * h1 + (1.f - z1) * t1;

    out[n + (size_t)node * 64 + lane]      = hn0;
    out[n + (size_t)node * 64 + lane + 32] = hn1;

    float dot = hn0 * sWo[lane] + hn1 * sWo[lane + 32];
    #pragma unroll
    for (int o = 16; o; o >>= 1) dot += __shfl_down_sync(0xffffffffu, dot, o);
    if (lane == 0) out[node] = dot + bo[0];
}

// ---------------- launcher ----------------
extern "C" void kernel_launch(void* const* d_in, const int* in_sizes, int n_in,
                              void* d_out, int out_size) {
    const float* x   = (const float*)d_in[0];
    const int*   ei  = (const int*)  d_in[1];
    const float* ew  = (const float*)d_in[2];
    const float* h   = (const float*)d_in[3];
    const float* Wz  = (const float*)d_in[4];
    const float* bz  = (const float*)d_in[5];
    const float* Wr  = (const float*)d_in[6];
    const float* br  = (const float*)d_in[7];
    const float* Wh  = (const float*)d_in[8];
    const float* bh  = (const float*)d_in[9];
    const float* Lz  = (const float*)d_in[10];
    const float* bLz = (const float*)d_in[11];
    const float* Lr  = (const float*)d_in[12];
    const float* bLr = (const float*)d_in[13];
    const float* Lh  = (const float*)d_in[14];
    const float* bLh = (const float*)d_in[15];
    const float* Wo  = (const float*)d_in[16];
    const float* bo  = (const float*)d_in[17];
    float* out = (float*)d_out;

    int N = in_sizes[0] / 128;
    int E = in_sizes[2];
    int setup_elems = (N > 192 * 192) ? N : 192 * 192;

    k_setup<<<(setup_elems + 255) / 256, 256>>>(Wz, Wr, Wh, Lz, Lr, Lh,
                                                bz, br, bh, bLz, bLr, bLh, N);
    k_hist<<<(E + 255) / 256, 256>>>(ei, ew, E);
    k_scan1<<<1, 1024>>>(N, E);
    k_fill<<<(E + 255) / 256, 256>>>(ei, ew, E);
    k_agg<<<(N + 7) / 8, 256>>>(x, h, N);
    k_gemm<<<(N + 127) / 128, 256>>>(N);
    k_final<<<(N + 7) / 8, 256>>>(h, Lh, Wo, bo, out, N);
}